// round 13
// baseline (speedup 1.0000x reference)
#include <cuda_runtime.h>
#include <cuda_fp16.h>
#include <math.h>
#include <stdint.h>

// ---------------------------------------------------------------------------
// QuantumKernelMethod: 4 qubits, 2 layers.
// z(i,j) = | u_i^H M_j u_i |, u_i = A(a_i)|0>, M_j = A(b_j) Z0 A(b_j)^H.
// A(x) = U_fixed * (tensor_q Ry(x_q)); U_fixed computed in-block (parallel).
// M = I - 2 B B^H, B = A[:,8:16].
// Gram = | F[1024x256] * G^T | via fp16 MMA (fp32 acc), single-wave GEMM,
// 512 threads, pipelined fragments (non-volatile asm so ptxas can schedule).
// ---------------------------------------------------------------------------

#define NROWS 1024
#define FDIM 256

__device__ __align__(16) __half g_F[NROWS * FDIM];
__device__ __align__(16) __half g_G[NROWS * FDIM];

// fused U(l,i) = Rz(c) Ry(b) Rx(a); lanes 0..7 compute one each
__device__ __forceinline__ void build_fused_mats(const float* params,
                                                 float2 (*shU)[4], int tid) {
    if (tid < 8) {
        float a = params[tid * 3 + 0], b = params[tid * 3 + 1], c = params[tid * 3 + 2];
        float sa, ca, sb, cb, sc, cc;
        __sincosf(0.5f * a, &sa, &ca);
        __sincosf(0.5f * b, &sb, &cb);
        __sincosf(0.5f * c, &sc, &cc);
        float2 m00 = make_float2(cb * ca,  sb * sa);
        float2 m01 = make_float2(-sb * ca, -cb * sa);
        float2 m10 = make_float2(sb * ca, -cb * sa);
        float2 m11 = make_float2(cb * ca, -sb * sa);
        shU[tid][0] = make_float2(cc * m00.x + sc * m00.y, cc * m00.y - sc * m00.x);
        shU[tid][1] = make_float2(cc * m01.x + sc * m01.y, cc * m01.y - sc * m01.x);
        shU[tid][2] = make_float2(cc * m10.x - sc * m10.y, cc * m10.y + sc * m10.x);
        shU[tid][3] = make_float2(cc * m11.x - sc * m11.y, cc * m11.y + sc * m11.x);
    }
}

// CNOT ring (0,1)(1,2)(2,3)(3,0) as a basis-index permutation
__device__ __forceinline__ int cnot_perm(int idx) {
    if (idx & 8) idx ^= 4;
    if (idx & 4) idx ^= 2;
    if (idx & 2) idx ^= 1;
    if (idx & 1) idx ^= 8;
    return idx;
}

// idx in [0,120) -> (p,q), p<q<16: sqrt seed + exact correction
__device__ __forceinline__ void pq_from_idx(int idx, int& p, int& q) {
    float d = 240.25f - 2.f * (float)idx;
    p = (int)(15.5f - sqrtf(d));
    if (p < 0) p = 0;
    int rem = idx - (15 * p - ((p * (p - 1)) >> 1));
    while (rem < 0) { p--; rem = idx - (15 * p - ((p * (p - 1)) >> 1)); }
    while (rem >= 15 - p) { rem -= 15 - p; p++; }
    q = p + 1 + rem;
}

// ---- build kernel: 192 blocks x 128 threads ---------------------------------
#define F_BLOCKS 64
#define G_BLOCKS 128

__global__ __launch_bounds__(128) void build_features(const float* __restrict__ a,
                                                      const float* __restrict__ b,
                                                      const float* __restrict__ params) {
    __shared__ float2 shU[8][4];
    __shared__ float2 shS[16][17];       // [column k][amp p] = U_fixed[p][k]
    __shared__ float2 sh_stF[16][16];
    __shared__ float2 sh_stG[8][16][9];
    __shared__ float  sh_f[16][256];

    int tid = threadIdx.x;
    build_fused_mats(params, shU, tid);

    // ---- in-block parallel U_fixed: 16 columns x 8 pairs ----
    {
        int ucol = tid & 15, pr = tid >> 4;
#pragma unroll
        for (int h = 0; h < 2; h++) {
            int amp = pr * 2 + h;
            shS[ucol][amp] = make_float2((amp == ucol) ? 1.f : 0.f, 0.f);
        }
        __syncthreads();

#pragma unroll
        for (int l = 0; l < 2; l++) {
#pragma unroll
            for (int i = 0; i < 4; i++) {
                int m = 8 >> i;
                int lo = pr & (m - 1);
                int idx0 = ((pr & ~(m - 1)) << 1) | lo;
                int idx1 = idx0 | m;

                float2 x0 = shS[ucol][idx0];
                float2 x1 = shS[ucol][idx1];
                float2 U00 = shU[l * 4 + i][0], U01 = shU[l * 4 + i][1];
                float2 U10 = shU[l * 4 + i][2], U11 = shU[l * 4 + i][3];
                float2 n0, n1;
                n0.x = U00.x * x0.x - U00.y * x0.y + U01.x * x1.x - U01.y * x1.y;
                n0.y = U00.x * x0.y + U00.y * x0.x + U01.x * x1.y + U01.y * x1.x;
                n1.x = U10.x * x0.x - U10.y * x0.y + U11.x * x1.x - U11.y * x1.y;
                n1.y = U10.x * x0.y + U10.y * x0.x + U11.x * x1.y + U11.y * x1.x;

                if (i == 3) {
                    __syncthreads();
                    shS[ucol][cnot_perm(idx0)] = n0;
                    shS[ucol][cnot_perm(idx1)] = n1;
                } else {
                    shS[ucol][idx0] = n0;
                    shS[ucol][idx1] = n1;
                }
                __syncthreads();
            }
        }
    }

    bool isF = blockIdx.x < F_BLOCKS;

    if (isF) {
        int g = tid >> 3, l = tid & 7;
        int row = blockIdx.x * 16 + g;
        float4 xv = *(const float4*)&a[row * 4];
        float cq[4], sq[4];
        __sincosf(0.5f * xv.x, &sq[0], &cq[0]);
        __sincosf(0.5f * xv.y, &sq[1], &cq[1]);
        __sincosf(0.5f * xv.z, &sq[2], &cq[2]);
        __sincosf(0.5f * xv.w, &sq[3], &cq[3]);

        float v[16];
#pragma unroll
        for (int k = 0; k < 16; k++) {
            float t0 = (k & 8) ? sq[0] : cq[0];
            float t1 = (k & 4) ? sq[1] : cq[1];
            float t2 = (k & 2) ? sq[2] : cq[2];
            float t3 = (k & 1) ? sq[3] : cq[3];
            v[k] = (t0 * t1) * (t2 * t3);
        }
#pragma unroll
        for (int h = 0; h < 2; h++) {
            int p = l + 8 * h;
            float ux = 0.f, uy = 0.f;
#pragma unroll
            for (int k = 0; k < 16; k++) {
                float2 Upk = shS[k][p];
                ux += Upk.x * v[k];
                uy += Upk.y * v[k];
            }
            sh_stF[g][p] = make_float2(ux, uy);
        }
        __syncthreads();

#pragma unroll
        for (int h = 0; h < 2; h++) {
            int p = l + 8 * h;
            float2 u = sh_stF[g][p];
            sh_f[g][p] = u.x * u.x + u.y * u.y;
        }
#pragma unroll
        for (int it = 0; it < 15; it++) {
            int idx = l + 8 * it;
            int p, q; pq_from_idx(idx, p, q);
            float2 up = sh_stF[g][p], uq = sh_stF[g][q];
            sh_f[g][16 + idx]  = 2.f * (up.x * uq.x + up.y * uq.y);
            sh_f[g][136 + idx] = 2.f * (up.y * uq.x - up.x * uq.y);
        }
        __syncthreads();

        __half2* dst = (__half2*)g_F;
        int r0 = blockIdx.x * 16;
#pragma unroll
        for (int it = 0; it < 16; it++) {
            int flat = it * 128 + tid;
            int rl = flat >> 7, t2 = flat & 127;
            __half2 o = __floats2half2_rn(sh_f[rl][2 * t2], sh_f[rl][2 * t2 + 1]);
            dst[(size_t)(r0 + rl) * (FDIM / 2) + t2] = o;
        }
    } else {
        int g = tid >> 4, l = tid & 15;
        int col = l & 7, half = l >> 3;
        int row = (blockIdx.x - F_BLOCKS) * 8 + g;
        float4 xv = *(const float4*)&b[row * 4];
        float cq[4], sq[4];
        __sincosf(0.5f * xv.x, &sq[0], &cq[0]);
        __sincosf(0.5f * xv.y, &sq[1], &cq[1]);
        __sincosf(0.5f * xv.z, &sq[2], &cq[2]);
        __sincosf(0.5f * xv.w, &sq[3], &cq[3]);

        float f0[4], f1[4];
        f0[0] = -sq[0]; f1[0] = cq[0];
#pragma unroll
        for (int q = 1; q < 4; q++) {
            int mq = (col >> (3 - q)) & 1;
            f0[q] = mq ? -sq[q] : cq[q];
            f1[q] = mq ?  cq[q] : sq[q];
        }
        float w[16];
#pragma unroll
        for (int k = 0; k < 16; k++) {
            float t0 = (k & 8) ? f1[0] : f0[0];
            float t1 = (k & 4) ? f1[1] : f0[1];
            float t2 = (k & 2) ? f1[2] : f0[2];
            float t3 = (k & 1) ? f1[3] : f0[3];
            w[k] = (t0 * t1) * (t2 * t3);
        }
#pragma unroll
        for (int pi = 0; pi < 8; pi++) {
            int p = half * 8 + pi;
            float ux = 0.f, uy = 0.f;
#pragma unroll
            for (int k = 0; k < 16; k++) {
                float2 Upk = shS[k][p];
                ux += Upk.x * w[k];
                uy += Upk.y * w[k];
            }
            sh_stG[g][p][col] = make_float2(ux, uy);
        }
        __syncthreads();

        {
            float s2 = 0.f;
#pragma unroll
            for (int k = 0; k < 8; k++) {
                float2 v2 = sh_stG[g][l][k];
                s2 += v2.x * v2.x + v2.y * v2.y;
            }
            sh_f[g][l] = 1.f - 2.f * s2;
        }
#pragma unroll
        for (int it = 0; it < 8; it++) {
            int idx = l + 16 * it;
            if (idx >= 120) break;
            int p, q; pq_from_idx(idx, p, q);
            float re = 0.f, im = 0.f;
#pragma unroll
            for (int k = 0; k < 8; k++) {
                float2 ap = sh_stG[g][p][k];
                float2 aq = sh_stG[g][q][k];
                re += ap.x * aq.x + ap.y * aq.y;
                im += ap.y * aq.x - ap.x * aq.y;
            }
            sh_f[g][16 + idx]  = -2.f * re;
            sh_f[g][136 + idx] = -2.f * im;
        }
        __syncthreads();

        __half2* dst = (__half2*)g_G;
        int r0 = (blockIdx.x - F_BLOCKS) * 8;
#pragma unroll
        for (int it = 0; it < 8; it++) {
            int flat = it * 128 + tid;
            int rl = flat >> 7, t2 = flat & 127;
            __half2 o = __floats2half2_rn(sh_f[rl][2 * t2], sh_f[rl][2 * t2 + 1]);
            dst[(size_t)(r0 + rl) * (FDIM / 2) + t2] = o;
        }
    }
}

// ---- fp16 NT GEMM: 128x64 tile, 512 threads, single wave, pipelined frags ---
// 16 warps (4m x 4n), warp tile 32x16, m16n8k16, fp32 acc, split-K overlap.
// ldmatrix/mma are NON-volatile so ptxas can software-pipeline the chains.

#define BM 128
#define BN 64
#define KPADH 264   // padded row stride in halves (rows -> distinct bank groups)
#define GEMM_SMEM ((BM + BN) * KPADH * 2)

__device__ __forceinline__ void cp_async16(void* smem_dst, const void* gmem_src) {
    uint32_t s = (uint32_t)__cvta_generic_to_shared(smem_dst);
    asm volatile("cp.async.ca.shared.global [%0], [%1], 16;" :: "r"(s), "l"(gmem_src));
}

__global__ __launch_bounds__(512) void gemm_f16_abs(float* __restrict__ C) {
    extern __shared__ __half smem[];
    __half* As = smem;                 // [BM][KPADH]
    __half* Bs = smem + BM * KPADH;    // [BN][KPADH]

    int tid = threadIdx.x;
    int warp = tid >> 5, lane = tid & 31;
    int wm = warp >> 2;          // 0..3
    int wn = warp & 3;           // 0..3
    int grp = lane >> 2;         // 0..7
    int tig = lane & 3;          // 0..3

    int i0 = blockIdx.y * BM;
    int j0 = blockIdx.x * BN;

    // ---- split-K loads: group0 = K[0,128), group1 = K[128,256) ----
#define LOAD_HALF(kh)                                                            \
    do {                                                                          \
        _Pragma("unroll")                                                         \
        for (int it = 0; it < 4; it++) {                                          \
            int c = it * 512 + tid;                                               \
            int r = c >> 4, s = c & 15;                                           \
            cp_async16(&As[r * KPADH + (kh) * 128 + s * 8],                       \
                       &g_F[(size_t)(i0 + r) * FDIM + (kh) * 128 + s * 8]);       \
        }                                                                         \
        _Pragma("unroll")                                                         \
        for (int it = 0; it < 2; it++) {                                          \
            int c = it * 512 + tid;                                               \
            int r = c >> 4, s = c & 15;                                           \
            cp_async16(&Bs[r * KPADH + (kh) * 128 + s * 8],                       \
                       &g_G[(size_t)(j0 + r) * FDIM + (kh) * 128 + s * 8]);       \
        }                                                                         \
        asm volatile("cp.async.commit_group;");                                   \
    } while (0)

    LOAD_HALF(0);
    LOAD_HALF(1);

    // ---- ldmatrix base addresses ----
    int a_r = (lane & 7) + ((lane >> 3) & 1) * 8;
    int a_c = ((lane >> 4) & 1) * 8;
    uint32_t a_base[2];
#pragma unroll
    for (int mt = 0; mt < 2; mt++)
        a_base[mt] = (uint32_t)__cvta_generic_to_shared(
            &As[(wm * 32 + mt * 16 + a_r) * KPADH + a_c]);
    int b_r = (lane & 7) + ((lane >> 4) & 1) * 8;
    int b_c = ((lane >> 3) & 1) * 8;
    uint32_t b_base = (uint32_t)__cvta_generic_to_shared(
        &Bs[(wn * 16 + b_r) * KPADH + b_c]);

    float acc[2][2][4];
#pragma unroll
    for (int mt = 0; mt < 2; mt++)
#pragma unroll
        for (int nt = 0; nt < 2; nt++)
#pragma unroll
            for (int r = 0; r < 4; r++) acc[mt][nt][r] = 0.f;

    // Fragment load: NON-volatile asm with memory clobber (ordered vs barriers,
    // schedulable vs MMAs).
#define LDFRAG(buf, k16_)                                                        \
    do {                                                                          \
        uint32_t koff = (uint32_t)((k16_) * 32);                                  \
        _Pragma("unroll")                                                         \
        for (int mt = 0; mt < 2; mt++) {                                          \
            asm("ldmatrix.sync.aligned.m8n8.x4.shared.b16 {%0,%1,%2,%3}, [%4];"   \
                : "=r"(afr[buf][mt][0]), "=r"(afr[buf][mt][1]),                   \
                  "=r"(afr[buf][mt][2]), "=r"(afr[buf][mt][3])                    \
                : "r"(a_base[mt] + koff) : "memory");                             \
        }                                                                         \
        asm("ldmatrix.sync.aligned.m8n8.x4.shared.b16 {%0,%1,%2,%3}, [%4];"       \
            : "=r"(bfr[buf][0][0]), "=r"(bfr[buf][0][1]),                         \
              "=r"(bfr[buf][1][0]), "=r"(bfr[buf][1][1])                          \
            : "r"(b_base + koff) : "memory");                                     \
    } while (0)

    // MMA: pure register dataflow, non-volatile -> ptxas schedules freely.
#define DO_MMAS(buf)                                                             \
    do {                                                                          \
        _Pragma("unroll")                                                         \
        for (int mt = 0; mt < 2; mt++)                                            \
            _Pragma("unroll")                                                     \
            for (int nt = 0; nt < 2; nt++) {                                      \
                asm("mma.sync.aligned.m16n8k16.row.col.f32.f16.f16.f32 "          \
                    "{%0,%1,%2,%3}, {%4,%5,%6,%7}, {%8,%9}, {%0,%1,%2,%3};"       \
                    : "+f"(acc[mt][nt][0]), "+f"(acc[mt][nt][1]),                 \
                      "+f"(acc[mt][nt][2]), "+f"(acc[mt][nt][3])                  \
                    : "r"(afr[buf][mt][0]), "r"(afr[buf][mt][1]),                 \
                      "r"(afr[buf][mt][2]), "r"(afr[buf][mt][3]),                 \
                      "r"(bfr[buf][nt][0]), "r"(bfr[buf][nt][1]));                \
            }                                                                     \
    } while (0)

    uint32_t afr[2][2][4], bfr[2][2][2];

    // ---- half 0 ----
    asm volatile("cp.async.wait_group 1;");
    __syncthreads();
    LDFRAG(0, 0);
#pragma unroll
    for (int k16 = 0; k16 < 8; k16++) {
        if (k16 < 7) LDFRAG((k16 + 1) & 1, k16 + 1);
        DO_MMAS(k16 & 1);
    }

    // ---- half 1 ----
    asm volatile("cp.async.wait_group 0;");
    __syncthreads();
    LDFRAG(0, 8);
#pragma unroll
    for (int k16 = 8; k16 < 16; k16++) {
        if (k16 < 15) LDFRAG((k16 + 1) & 1, k16 + 1);
        DO_MMAS(k16 & 1);
    }

    // ---- epilogue ----
#pragma unroll
    for (int mt = 0; mt < 2; mt++) {
        int rowg = i0 + wm * 32 + mt * 16 + grp;
#pragma unroll
        for (int nt = 0; nt < 2; nt++) {
            int colg = j0 + wn * 16 + nt * 8 + 2 * tig;
            float2 o0 = make_float2(fabsf(acc[mt][nt][0]), fabsf(acc[mt][nt][1]));
            float2 o1 = make_float2(fabsf(acc[mt][nt][2]), fabsf(acc[mt][nt][3]));
            *(float2*)&C[(size_t)rowg * NROWS + colg] = o0;
            *(float2*)&C[(size_t)(rowg + 8) * NROWS + colg] = o1;
        }
    }
}

// ---------------------------------------------------------------------------
extern "C" void kernel_launch(void* const* d_in, const int* in_sizes, int n_in,
                              void* d_out, int out_size) {
    const float* a = (const float*)d_in[0];       // [1024,4]
    const float* b = (const float*)d_in[1];       // [1024,4]
    const float* params = (const float*)d_in[2];  // [2,4,3]
    float* out = (float*)d_out;                   // [1024,1024]

    cudaFuncSetAttribute(gemm_f16_abs,
                         cudaFuncAttributeMaxDynamicSharedMemorySize, GEMM_SMEM);

    build_features<<<F_BLOCKS + G_BLOCKS, 128>>>(a, b, params);

    dim3 grid(NROWS / BN, NROWS / BM);   // (16, 8) = 128 blocks, single wave
    gemm_f16_abs<<<grid, 512, GEMM_SMEM>>>(out);
}

// round 14
// speedup vs baseline: 1.0426x; 1.0426x over previous
#include <cuda_runtime.h>
#include <cuda_fp16.h>
#include <math.h>
#include <stdint.h>

// ---------------------------------------------------------------------------
// QuantumKernelMethod: 4 qubits, 2 layers.
// z(i,j) = | u_i^H M_j u_i |, u_i = A(a_i)|0>, M_j = A(b_j) Z0 A(b_j)^H.
// A(x) = U_fixed * (tensor_q Ry(x_q)); U_fixed computed in-block (parallel).
// M = I - 2 B B^H, B = A[:,8:16].
// Gram = | F[1024x256] * G^T |, fp16 MMA (fp32 acc).
// GEMM tiles are loaded with cp.async.bulk (2 copies/block instead of 6144
// scalar cp.asyncs -- the former LDGSTS-issue floor). Feature rows are stored
// XOR-swizzled (16B chunk ^ (row&7)) so ldmatrix stays bank-conflict-free
// without smem padding (bulk copy is verbatim).
// ---------------------------------------------------------------------------

#define NROWS 1024
#define FDIM 256
#define ROW_HALVES 256           // halves per feature row
#define ROW_BYTES  512

__device__ __align__(16) __half g_F[NROWS * FDIM];
__device__ __align__(16) __half g_G[NROWS * FDIM];

// swizzled half2-index within a row: chunk(16B) index ^= (row & 7)
__device__ __forceinline__ int sw_t2(int row, int t2) {
    return ((((t2 >> 2) ^ (row & 7)) << 2) | (t2 & 3));
}

// fused U(l,i) = Rz(c) Ry(b) Rx(a); lanes 0..7 compute one each
__device__ __forceinline__ void build_fused_mats(const float* params,
                                                 float2 (*shU)[4], int tid) {
    if (tid < 8) {
        float a = params[tid * 3 + 0], b = params[tid * 3 + 1], c = params[tid * 3 + 2];
        float sa, ca, sb, cb, sc, cc;
        __sincosf(0.5f * a, &sa, &ca);
        __sincosf(0.5f * b, &sb, &cb);
        __sincosf(0.5f * c, &sc, &cc);
        float2 m00 = make_float2(cb * ca,  sb * sa);
        float2 m01 = make_float2(-sb * ca, -cb * sa);
        float2 m10 = make_float2(sb * ca, -cb * sa);
        float2 m11 = make_float2(cb * ca, -sb * sa);
        shU[tid][0] = make_float2(cc * m00.x + sc * m00.y, cc * m00.y - sc * m00.x);
        shU[tid][1] = make_float2(cc * m01.x + sc * m01.y, cc * m01.y - sc * m01.x);
        shU[tid][2] = make_float2(cc * m10.x - sc * m10.y, cc * m10.y + sc * m10.x);
        shU[tid][3] = make_float2(cc * m11.x - sc * m11.y, cc * m11.y + sc * m11.x);
    }
}

// CNOT ring (0,1)(1,2)(2,3)(3,0) as a basis-index permutation
__device__ __forceinline__ int cnot_perm(int idx) {
    if (idx & 8) idx ^= 4;
    if (idx & 4) idx ^= 2;
    if (idx & 2) idx ^= 1;
    if (idx & 1) idx ^= 8;
    return idx;
}

// idx in [0,120) -> (p,q), p<q<16: sqrt seed + exact correction
__device__ __forceinline__ void pq_from_idx(int idx, int& p, int& q) {
    float d = 240.25f - 2.f * (float)idx;
    p = (int)(15.5f - sqrtf(d));
    if (p < 0) p = 0;
    int rem = idx - (15 * p - ((p * (p - 1)) >> 1));
    while (rem < 0) { p--; rem = idx - (15 * p - ((p * (p - 1)) >> 1)); }
    while (rem >= 15 - p) { rem -= 15 - p; p++; }
    q = p + 1 + rem;
}

// ---- build kernel: 192 blocks x 128 threads ---------------------------------
#define F_BLOCKS 64
#define G_BLOCKS 128

__global__ __launch_bounds__(128) void build_features(const float* __restrict__ a,
                                                      const float* __restrict__ b,
                                                      const float* __restrict__ params) {
    __shared__ float2 shU[8][4];
    __shared__ float2 shS[16][17];       // [column k][amp p] = U_fixed[p][k]
    __shared__ float2 sh_stF[16][16];
    __shared__ float2 sh_stG[8][16][9];
    __shared__ float  sh_f[16][256];

    int tid = threadIdx.x;
    build_fused_mats(params, shU, tid);

    // ---- in-block parallel U_fixed: 16 columns x 8 pairs ----
    {
        int ucol = tid & 15, pr = tid >> 4;
#pragma unroll
        for (int h = 0; h < 2; h++) {
            int amp = pr * 2 + h;
            shS[ucol][amp] = make_float2((amp == ucol) ? 1.f : 0.f, 0.f);
        }
        __syncthreads();

#pragma unroll
        for (int l = 0; l < 2; l++) {
#pragma unroll
            for (int i = 0; i < 4; i++) {
                int m = 8 >> i;
                int lo = pr & (m - 1);
                int idx0 = ((pr & ~(m - 1)) << 1) | lo;
                int idx1 = idx0 | m;

                float2 x0 = shS[ucol][idx0];
                float2 x1 = shS[ucol][idx1];
                float2 U00 = shU[l * 4 + i][0], U01 = shU[l * 4 + i][1];
                float2 U10 = shU[l * 4 + i][2], U11 = shU[l * 4 + i][3];
                float2 n0, n1;
                n0.x = U00.x * x0.x - U00.y * x0.y + U01.x * x1.x - U01.y * x1.y;
                n0.y = U00.x * x0.y + U00.y * x0.x + U01.x * x1.y + U01.y * x1.x;
                n1.x = U10.x * x0.x - U10.y * x0.y + U11.x * x1.x - U11.y * x1.y;
                n1.y = U10.x * x0.y + U10.y * x0.x + U11.x * x1.y + U11.y * x1.x;

                if (i == 3) {
                    __syncthreads();
                    shS[ucol][cnot_perm(idx0)] = n0;
                    shS[ucol][cnot_perm(idx1)] = n1;
                } else {
                    shS[ucol][idx0] = n0;
                    shS[ucol][idx1] = n1;
                }
                __syncthreads();
            }
        }
    }

    bool isF = blockIdx.x < F_BLOCKS;

    if (isF) {
        int g = tid >> 3, l = tid & 7;
        int row = blockIdx.x * 16 + g;
        float4 xv = *(const float4*)&a[row * 4];
        float cq[4], sq[4];
        __sincosf(0.5f * xv.x, &sq[0], &cq[0]);
        __sincosf(0.5f * xv.y, &sq[1], &cq[1]);
        __sincosf(0.5f * xv.z, &sq[2], &cq[2]);
        __sincosf(0.5f * xv.w, &sq[3], &cq[3]);

        float v[16];
#pragma unroll
        for (int k = 0; k < 16; k++) {
            float t0 = (k & 8) ? sq[0] : cq[0];
            float t1 = (k & 4) ? sq[1] : cq[1];
            float t2 = (k & 2) ? sq[2] : cq[2];
            float t3 = (k & 1) ? sq[3] : cq[3];
            v[k] = (t0 * t1) * (t2 * t3);
        }
#pragma unroll
        for (int h = 0; h < 2; h++) {
            int p = l + 8 * h;
            float ux = 0.f, uy = 0.f;
#pragma unroll
            for (int k = 0; k < 16; k++) {
                float2 Upk = shS[k][p];
                ux += Upk.x * v[k];
                uy += Upk.y * v[k];
            }
            sh_stF[g][p] = make_float2(ux, uy);
        }
        __syncthreads();

#pragma unroll
        for (int h = 0; h < 2; h++) {
            int p = l + 8 * h;
            float2 u = sh_stF[g][p];
            sh_f[g][p] = u.x * u.x + u.y * u.y;
        }
#pragma unroll
        for (int it = 0; it < 15; it++) {
            int idx = l + 8 * it;
            int p, q; pq_from_idx(idx, p, q);
            float2 up = sh_stF[g][p], uq = sh_stF[g][q];
            sh_f[g][16 + idx]  = 2.f * (up.x * uq.x + up.y * uq.y);
            sh_f[g][136 + idx] = 2.f * (up.y * uq.x - up.x * uq.y);
        }
        __syncthreads();

        // swizzled half2 write
        __half2* dst = (__half2*)g_F;
        int r0 = blockIdx.x * 16;
#pragma unroll
        for (int it = 0; it < 16; it++) {
            int flat = it * 128 + tid;
            int rl = flat >> 7, t2 = flat & 127;
            __half2 o = __floats2half2_rn(sh_f[rl][2 * t2], sh_f[rl][2 * t2 + 1]);
            int row_g = r0 + rl;
            dst[(size_t)row_g * (ROW_HALVES / 2) + sw_t2(row_g, t2)] = o;
        }
    } else {
        int g = tid >> 4, l = tid & 15;
        int col = l & 7, half = l >> 3;
        int row = (blockIdx.x - F_BLOCKS) * 8 + g;
        float4 xv = *(const float4*)&b[row * 4];
        float cq[4], sq[4];
        __sincosf(0.5f * xv.x, &sq[0], &cq[0]);
        __sincosf(0.5f * xv.y, &sq[1], &cq[1]);
        __sincosf(0.5f * xv.z, &sq[2], &cq[2]);
        __sincosf(0.5f * xv.w, &sq[3], &cq[3]);

        float f0[4], f1[4];
        f0[0] = -sq[0]; f1[0] = cq[0];
#pragma unroll
        for (int q = 1; q < 4; q++) {
            int mq = (col >> (3 - q)) & 1;
            f0[q] = mq ? -sq[q] : cq[q];
            f1[q] = mq ?  cq[q] : sq[q];
        }
        float w[16];
#pragma unroll
        for (int k = 0; k < 16; k++) {
            float t0 = (k & 8) ? f1[0] : f0[0];
            float t1 = (k & 4) ? f1[1] : f0[1];
            float t2 = (k & 2) ? f1[2] : f0[2];
            float t3 = (k & 1) ? f1[3] : f0[3];
            w[k] = (t0 * t1) * (t2 * t3);
        }
#pragma unroll
        for (int pi = 0; pi < 8; pi++) {
            int p = half * 8 + pi;
            float ux = 0.f, uy = 0.f;
#pragma unroll
            for (int k = 0; k < 16; k++) {
                float2 Upk = shS[k][p];
                ux += Upk.x * w[k];
                uy += Upk.y * w[k];
            }
            sh_stG[g][p][col] = make_float2(ux, uy);
        }
        __syncthreads();

        {
            float s2 = 0.f;
#pragma unroll
            for (int k = 0; k < 8; k++) {
                float2 v2 = sh_stG[g][l][k];
                s2 += v2.x * v2.x + v2.y * v2.y;
            }
            sh_f[g][l] = 1.f - 2.f * s2;
        }
#pragma unroll
        for (int it = 0; it < 8; it++) {
            int idx = l + 16 * it;
            if (idx >= 120) break;
            int p, q; pq_from_idx(idx, p, q);
            float re = 0.f, im = 0.f;
#pragma unroll
            for (int k = 0; k < 8; k++) {
                float2 ap = sh_stG[g][p][k];
                float2 aq = sh_stG[g][q][k];
                re += ap.x * aq.x + ap.y * aq.y;
                im += ap.y * aq.x - ap.x * aq.y;
            }
            sh_f[g][16 + idx]  = -2.f * re;
            sh_f[g][136 + idx] = -2.f * im;
        }
        __syncthreads();

        __half2* dst = (__half2*)g_G;
        int r0 = (blockIdx.x - F_BLOCKS) * 8;
#pragma unroll
        for (int it = 0; it < 8; it++) {
            int flat = it * 128 + tid;
            int rl = flat >> 7, t2 = flat & 127;
            __half2 o = __floats2half2_rn(sh_f[rl][2 * t2], sh_f[rl][2 * t2 + 1]);
            int row_g = r0 + rl;
            dst[(size_t)row_g * (ROW_HALVES / 2) + sw_t2(row_g, t2)] = o;
        }
    }
}

// ---- fp16 NT GEMM: 128x64 tile, 512 threads, bulk-copy loads ----------------
// 16 warps (4m x 4n), warp tile 32x16, m16n8k16, fp32 acc.
// A tile (64KB) and B tile (32KB) are each ONE cp.async.bulk (contiguous gmem).

#define BM 128
#define BN 64
#define A_BYTES (BM * ROW_BYTES)     // 65536
#define B_BYTES (BN * ROW_BYTES)     // 32768
#define GEMM_SMEM (A_BYTES + B_BYTES + 16)   // + mbarrier

__global__ __launch_bounds__(512) void gemm_f16_abs(float* __restrict__ C) {
    extern __shared__ __align__(16) __half smem[];
    __half* As = smem;                        // [BM][256] swizzled rows
    __half* Bs = smem + BM * ROW_HALVES;      // [BN][256]
    uint64_t* mbar = (uint64_t*)(smem + (BM + BN) * ROW_HALVES);

    int tid = threadIdx.x;
    int warp = tid >> 5, lane = tid & 31;
    int wm = warp >> 2;          // 0..3
    int wn = warp & 3;           // 0..3
    int grp = lane >> 2;         // 0..7
    int tig = lane & 3;          // 0..3

    int i0 = blockIdx.y * BM;
    int j0 = blockIdx.x * BN;

    uint32_t mbar_addr = (uint32_t)__cvta_generic_to_shared(mbar);
    uint32_t as_addr = (uint32_t)__cvta_generic_to_shared(As);
    uint32_t bs_addr = (uint32_t)__cvta_generic_to_shared(Bs);

    if (tid == 0) {
        asm volatile("mbarrier.init.shared.b64 [%0], 1;" :: "r"(mbar_addr) : "memory");
    }
    __syncthreads();

    if (tid == 0) {
        asm volatile("mbarrier.arrive.expect_tx.shared.b64 _, [%0], %1;"
                     :: "r"(mbar_addr), "r"((uint32_t)(A_BYTES + B_BYTES)) : "memory");
        asm volatile(
            "cp.async.bulk.shared::cta.global.mbarrier::complete_tx::bytes "
            "[%0], [%1], %2, [%3];"
            :: "r"(as_addr), "l"(&g_F[(size_t)i0 * ROW_HALVES]),
               "r"((uint32_t)A_BYTES), "r"(mbar_addr) : "memory");
        asm volatile(
            "cp.async.bulk.shared::cta.global.mbarrier::complete_tx::bytes "
            "[%0], [%1], %2, [%3];"
            :: "r"(bs_addr), "l"(&g_G[(size_t)j0 * ROW_HALVES]),
               "r"((uint32_t)B_BYTES), "r"(mbar_addr) : "memory");
    }

    // ---- ldmatrix lane roles (x4 layout) ----
    // A mats: (m0,k0),(m8,k0),(m0,k8),(m8,k8); lane -> row a_r, kchunk a_ck
    int a_r = (lane & 7) + ((lane >> 3) & 1) * 8;
    int a_ck = (lane >> 4) & 1;           // 16B chunk within k16 step
    // B mats: (n0,k0),(n0,k8),(n8,k0),(n8,k8) -> {r0,r1}=nt0, {r2,r3}=nt1
    int b_r = (lane & 7) + ((lane >> 4) & 1) * 8;
    int b_ck = (lane >> 3) & 1;

    // precompute row bases (swizzle applied per-k16 on chunk index)
    uint32_t a_rowaddr[2]; int a_rm[2];
#pragma unroll
    for (int mt = 0; mt < 2; mt++) {
        int row = wm * 32 + mt * 16 + a_r;
        a_rowaddr[mt] = as_addr + row * ROW_BYTES;
        a_rm[mt] = row & 7;
    }
    int b_row = wn * 16 + b_r;
    uint32_t b_rowaddr = bs_addr + b_row * ROW_BYTES;
    int b_rm = b_row & 7;

    float acc[2][2][4];
#pragma unroll
    for (int mt = 0; mt < 2; mt++)
#pragma unroll
        for (int nt = 0; nt < 2; nt++)
#pragma unroll
            for (int r = 0; r < 4; r++) acc[mt][nt][r] = 0.f;

    // wait for bulk copies
    {
        uint32_t done;
        asm volatile(
            "{\n\t.reg .pred p;\n\t"
            "mbarrier.try_wait.parity.shared.b64 p, [%1], 0;\n\t"
            "selp.b32 %0, 1, 0, p;\n\t}"
            : "=r"(done) : "r"(mbar_addr) : "memory");
        while (!done) {
            asm volatile(
                "{\n\t.reg .pred p;\n\t"
                "mbarrier.try_wait.parity.shared.b64 p, [%1], 0;\n\t"
                "selp.b32 %0, 1, 0, p;\n\t}"
                : "=r"(done) : "r"(mbar_addr) : "memory");
        }
    }
    __syncthreads();

    // ---- mainloop: 16 k16 steps ----
#pragma unroll
    for (int k16 = 0; k16 < 16; k16++) {
        uint32_t afr[2][4], bfr[2][2];
#pragma unroll
        for (int mt = 0; mt < 2; mt++) {
            uint32_t addr = a_rowaddr[mt] +
                (uint32_t)((((2 * k16 + a_ck) ^ a_rm[mt]) << 4));
            asm("ldmatrix.sync.aligned.m8n8.x4.shared.b16 {%0,%1,%2,%3}, [%4];"
                : "=r"(afr[mt][0]), "=r"(afr[mt][1]),
                  "=r"(afr[mt][2]), "=r"(afr[mt][3])
                : "r"(addr) : "memory");
        }
        {
            uint32_t addr = b_rowaddr +
                (uint32_t)((((2 * k16 + b_ck) ^ b_rm) << 4));
            asm("ldmatrix.sync.aligned.m8n8.x4.shared.b16 {%0,%1,%2,%3}, [%4];"
                : "=r"(bfr[0][0]), "=r"(bfr[0][1]),
                  "=r"(bfr[1][0]), "=r"(bfr[1][1])
                : "r"(addr) : "memory");
        }
#pragma unroll
        for (int mt = 0; mt < 2; mt++)
#pragma unroll
            for (int nt = 0; nt < 2; nt++) {
                asm("mma.sync.aligned.m16n8k16.row.col.f32.f16.f16.f32 "
                    "{%0,%1,%2,%3}, {%4,%5,%6,%7}, {%8,%9}, {%0,%1,%2,%3};"
                    : "+f"(acc[mt][nt][0]), "+f"(acc[mt][nt][1]),
                      "+f"(acc[mt][nt][2]), "+f"(acc[mt][nt][3])
                    : "r"(afr[mt][0]), "r"(afr[mt][1]),
                      "r"(afr[mt][2]), "r"(afr[mt][3]),
                      "r"(bfr[nt][0]), "r"(bfr[nt][1]));
            }
    }

    // ---- epilogue ----
#pragma unroll
    for (int mt = 0; mt < 2; mt++) {
        int rowg = i0 + wm * 32 + mt * 16 + grp;
#pragma unroll
        for (int nt = 0; nt < 2; nt++) {
            int colg = j0 + wn * 16 + nt * 8 + 2 * tig;
            float2 o0 = make_float2(fabsf(acc[mt][nt][0]), fabsf(acc[mt][nt][1]));
            float2 o1 = make_float2(fabsf(acc[mt][nt][2]), fabsf(acc[mt][nt][3]));
            *(float2*)&C[(size_t)rowg * NROWS + colg] = o0;
            *(float2*)&C[(size_t)(rowg + 8) * NROWS + colg] = o1;
        }
    }
}

// ---------------------------------------------------------------------------
extern "C" void kernel_launch(void* const* d_in, const int* in_sizes, int n_in,
                              void* d_out, int out_size) {
    const float* a = (const float*)d_in[0];       // [1024,4]
    const float* b = (const float*)d_in[1];       // [1024,4]
    const float* params = (const float*)d_in[2];  // [2,4,3]
    float* out = (float*)d_out;                   // [1024,1024]

    cudaFuncSetAttribute(gemm_f16_abs,
                         cudaFuncAttributeMaxDynamicSharedMemorySize, GEMM_SMEM);

    build_features<<<F_BLOCKS + G_BLOCKS, 128>>>(a, b, params);

    dim3 grid(NROWS / BN, NROWS / BM);   // (16, 8) = 128 blocks, single wave
    gemm_f16_abs<<<grid, 512, GEMM_SMEM>>>(out);
}